// round 3
// baseline (speedup 1.0000x reference)
#include <cuda_runtime.h>
#include <math.h>

// SetConv2dEncoder via Gaussian product factorization:
//   out[b,k,i,j] = C(i-j) * G[b,k,i+j]
//   C(d)     = exp(-(d*step)^2 / (4 s2))                  (uniform grid!)
//   G[b,k,s] = sum_n zc[b,n,k] * exp(-(p_s - u_n)^2 / s2), p_s=(x_i+x_j)/2
// kernel_G builds G (and the C difference table); kernel_out tiles 8 rows x
// 512 cols per block, stages G+C in smem, and streams pure DRAM writes.

#define S_PAD   2048
#define NCH     17
#define EPS_DEN 1e-8f
#define CT_N    2080
#define GW      544          // smem window: 512 cols + 28 row span + pad

__device__ __align__(16) float g_G[4 * NCH * S_PAD];
__device__ __align__(16) float g_ct[CT_N];    // g_ct[y] = C(y - 1024)

// ---------------------------------------------------------------------------
// Kernel A: G table. Lanes = 32 consecutive s (warp-uniform z loads), 8 warps
// split n, smem reduce. Extra block (bx==gridDim.x-1, bb==0) fills the C table.
// ---------------------------------------------------------------------------
__global__ void __launch_bounds__(256) kernel_G(
    const float* __restrict__ xz, const float* __restrict__ z,
    const float* __restrict__ x_grid, const float* __restrict__ log_scale,
    int n, int m)
{
    const int S    = 2 * m - 1;
    const int t    = threadIdx.x;
    const int lane = t & 31;
    const int w    = t >> 5;
    const int bb   = blockIdx.y;

    const float s2     = __expf(2.0f * log_scale[0]);
    const float inv_s2 = 1.0f / s2;

    if (blockIdx.x == (unsigned)((S + 31) / 32)) {       // C-table block
        if (bb == 0) {
            const float step = (x_grid[m - 1] - x_grid[0]) / (float)(m - 1);
            const float inv4 = 0.25f * inv_s2;
            for (int y = t; y < CT_N; y += 256) {
                float d = (float)(y - 1024) * step;
                g_ct[y] = __expf(-d * d * inv4);
            }
        }
        return;
    }

    const int s  = blockIdx.x * 32 + lane;
    const int se = (s < S) ? s : (S - 1);
    const int s0 = se >> 1;
    const float p = 0.5f * (x_grid[s0] + x_grid[se - s0]);
    const float thresh = 80.0f * s2;

    float acc[NCH];
#pragma unroll
    for (int k = 0; k < NCH; k++) acc[k] = 0.0f;

    const float* __restrict__ xzb = xz + (size_t)bb * n;
    const float* __restrict__ zb  = z  + (size_t)bb * n * 16;

    const int nc = n >> 3;           // per-warp n chunk
    const int n0 = w * nc;
#pragma unroll 4
    for (int nn = n0; nn < n0 + nc; nn++) {
        float u  = __ldg(xzb + nn);                    // warp-uniform
        float d  = p - u;
        float d2 = d * d;
        if (__ballot_sync(0xffffffffu, d2 < thresh)) {
            float e = __expf(-d2 * inv_s2);
            const float4* zr = (const float4*)(zb + ((size_t)nn << 4));
            float4 z0 = zr[0], z1 = zr[1], z2 = zr[2], z3 = zr[3];
            acc[0]  += e;
            acc[1]  += e * z0.x; acc[2]  += e * z0.y; acc[3]  += e * z0.z; acc[4]  += e * z0.w;
            acc[5]  += e * z1.x; acc[6]  += e * z1.y; acc[7]  += e * z1.z; acc[8]  += e * z1.w;
            acc[9]  += e * z2.x; acc[10] += e * z2.y; acc[11] += e * z2.z; acc[12] += e * z2.w;
            acc[13] += e * z3.x; acc[14] += e * z3.y; acc[15] += e * z3.z; acc[16] += e * z3.w;
        }
    }

    __shared__ float red[8][32][NCH];
#pragma unroll
    for (int k = 0; k < NCH; k++) red[w][lane][k] = acc[k];
    __syncthreads();

    const int sbase = blockIdx.x * 32;
    for (int idx = t; idx < 32 * NCH; idx += 256) {
        int ln = idx & 31, k = idx >> 5;
        int ss = sbase + ln;
        if (ss < S) {
            float v = 0.0f;
#pragma unroll
            for (int ww = 0; ww < 8; ww++) v += red[ww][ln][k];
            g_G[((size_t)bb * NCH + k) * S_PAD + ss] = v;
        }
    }
}

// ---------------------------------------------------------------------------
// Kernel B: block = (8 rows stride-4, 512 cols, batch). Stage G window +
// C-diff window into smem; then exp-free streaming writes (18 STG.128/row).
// bx in [0,256): jh=bx&1 (col half), gx=bx>>1: i_base=(gx>>2)*32+(gx&3).
// ---------------------------------------------------------------------------
__global__ void __launch_bounds__(256) kernel_out(
    float* __restrict__ out, int m)
{
    __shared__ float gs[NCH * GW];
    __shared__ float cs[GW];

    const int t  = threadIdx.x;
    const int bb = blockIdx.y;
    const int bx = blockIdx.x;
    const int jb = (bx & 1) * (m >> 1);
    const int gx = bx >> 1;
    const int ib = (gx >> 2) * 32 + (gx & 3);
    const int sb = ib + jb;

    // stage G window: gs[k][x] = G[b,k,sb+x], x in [0, 540)
    const float* __restrict__ Gb = g_G + (size_t)bb * NCH * S_PAD + sb;
#pragma unroll
    for (int k = 0; k < NCH; k++)
        for (int x = t; x < GW; x += 256)
            gs[k * GW + x] = Gb[k * S_PAD + x];

    // stage C window: cs[u] = C(K - u), K = ib - jb + 28
    const int K = ib - jb + 28;
    for (int x = t; x < GW; x += 256) {
        int y = K + 1024 - x;
        cs[x] = (y >= 0 && y < CT_N) ? g_ct[y] : 0.0f;
    }
    __syncthreads();

    const int tj = t & 127;          // column group: j = jb + 4*tj + q
    const int rh = t >> 7;           // row parity
    const int jof = tj << 2;
    const size_t chs = (size_t)m * m;

#pragma unroll
    for (int rr = 0; rr < 4; rr++) {
        const int r = rh + 2 * rr;           // row index 0..7
        const int i = ib + 4 * r;

        const float4 c4 = *(const float4*)&cs[28 - 4 * r + jof];
        const float4 g0 = *(const float4*)&gs[4 * r + jof];

        float* op = out + (((size_t)bb * 18) * m + i) * m + jb + jof;

        float4 v;
        // ch0: identity
        const int jg = jb + jof;
        v.x = (jg     == i) ? 1.0f : 0.0f;
        v.y = (jg + 1 == i) ? 1.0f : 0.0f;
        v.z = (jg + 2 == i) ? 1.0f : 0.0f;
        v.w = (jg + 3 == i) ? 1.0f : 0.0f;
        __stcs((float4*)op, v);

        // ch1: density = C * G0
        float d0 = c4.x * g0.x, d1 = c4.y * g0.y, d2 = c4.z * g0.z, d3 = c4.w * g0.w;
        v.x = d0; v.y = d1; v.z = d2; v.w = d3;
        __stcs((float4*)(op + chs), v);

        // ch2..17: Gk * (C / (density + eps))
        float q0 = __fdividef(c4.x, d0 + EPS_DEN);
        float q1 = __fdividef(c4.y, d1 + EPS_DEN);
        float q2 = __fdividef(c4.z, d2 + EPS_DEN);
        float q3 = __fdividef(c4.w, d3 + EPS_DEN);

#pragma unroll
        for (int k = 1; k < NCH; k++) {
            const float4 gk = *(const float4*)&gs[k * GW + 4 * r + jof];
            v.x = gk.x * q0;
            v.y = gk.y * q1;
            v.z = gk.z * q2;
            v.w = gk.w * q3;
            __stcs((float4*)(op + (size_t)(k + 1) * chs), v);
        }
    }
}

// ---------------------------------------------------------------------------
extern "C" void kernel_launch(void* const* d_in, const int* in_sizes, int n_in,
                              void* d_out, int out_size)
{
    const float* xz        = (const float*)d_in[0];
    const float* z         = (const float*)d_in[1];
    const float* x_grid    = (const float*)d_in[2];
    const float* log_scale = (const float*)d_in[3];

    const int m = in_sizes[2];
    const long long xz_sz = in_sizes[0];
    const long long z_sz  = in_sizes[1];
    const int c = (int)(z_sz / xz_sz);                        // 16
    const long long per_b = (long long)(c + 2) * m * m;       // 18*m*m
    const long long b     = (long long)out_size / per_b;      // 4
    const long long header = (long long)out_size - b * per_b; // leading x_grid
    const int n = (int)(xz_sz / b);

    float* outp = (float*)d_out;
    if (header > 0) {
        cudaMemcpyAsync(outp, x_grid, (size_t)header * sizeof(float),
                        cudaMemcpyDeviceToDevice, 0);
        outp += header;
    }

    const int S = 2 * m - 1;
    dim3 gA((unsigned)((S + 31) / 32) + 1, (unsigned)b);   // +1: C-table block
    kernel_G<<<gA, 256>>>(xz, z, x_grid, log_scale, n, m);

    dim3 gB((unsigned)((m / 32) * 4 * 2), (unsigned)b);    // 256 x 4
    kernel_out<<<gB, 256>>>(outp, m);
}

// round 4
// speedup vs baseline: 1.1073x; 1.1073x over previous
#include <cuda_runtime.h>
#include <math.h>

// SetConv2dEncoder via Gaussian product factorization:
//   out[b,k,i,j] = C(i,j) * G[b,k,i+j],  C = exp(-(xi-xj)^2/(4 s2)),
//   G[b,k,s]     = sum_n zc[b,n,k] * exp(-(p_s - u_n)^2 / s2)
// kernel_G builds the midpoint table (4 rotated copies -> kernel_out gets
// aligned float4 loads); kernel_out streams the 302MB output, 2 rows/block.

#define S_PAD   2048
#define NCH     17
#define EPS_DEN 1e-8f

// 4 batches x 4 rotations x 17 ch x 2048: copy r holds G[s] at index s-r.
__device__ __align__(16) float g_G4[4 * 4 * NCH * S_PAD];

// ---------------------------------------------------------------------------
// Kernel A: lanes = 32 consecutive s (warp-uniform z loads), 8 warps split n.
// xz read as float4 (4 u's per LDG.128, one ballot per group). Ballot skips
// inactive groups (Gaussian support ~16% of the domain).
// ---------------------------------------------------------------------------
__global__ void __launch_bounds__(256) kernel_G(
    const float* __restrict__ xz, const float* __restrict__ z,
    const float* __restrict__ x_grid, const float* __restrict__ log_scale,
    int n, int m)
{
    const int S    = 2 * m - 1;
    const int t    = threadIdx.x;
    const int lane = t & 31;
    const int w    = t >> 5;
    const int bb   = blockIdx.y;

    const int s  = blockIdx.x * 32 + lane;
    const int se = (s < S) ? s : (S - 1);
    const int s0 = se >> 1;

    const float s2     = __expf(2.0f * log_scale[0]);
    const float inv_s2 = 1.0f / s2;
    const float thresh = 80.0f * s2;          // exp(-80): negligible
    const float p      = 0.5f * (x_grid[s0] + x_grid[se - s0]);

    float acc[NCH];
#pragma unroll
    for (int k = 0; k < NCH; k++) acc[k] = 0.0f;

    const float* __restrict__ xzb = xz + (size_t)bb * n;
    const float* __restrict__ zb  = z  + (size_t)bb * n * 16;

    const int nc = n >> 3;                    // per-warp n chunk (128)
    const int n0 = w * nc;
    const float4* __restrict__ xz4 = (const float4*)(xzb + n0);

#pragma unroll 2
    for (int g = 0; g < (nc >> 2); g++) {
        const float4 u4 = __ldg(xz4 + g);     // warp-uniform broadcast
        float da = p - u4.x, db = p - u4.y, dc = p - u4.z, dd = p - u4.w;
        float a0 = da * da, a1 = db * db, a2 = dc * dc, a3 = dd * dd;
        bool any = (a0 < thresh) | (a1 < thresh) | (a2 < thresh) | (a3 < thresh);
        if (__ballot_sync(0xffffffffu, any)) {
            const int nn = n0 + (g << 2);
#pragma unroll
            for (int e4 = 0; e4 < 4; e4++) {
                float a = (e4 == 0) ? a0 : (e4 == 1) ? a1 : (e4 == 2) ? a2 : a3;
                float e = __expf(-a * inv_s2);      // underflows to 0 if inactive
                const float4* zr = (const float4*)(zb + ((size_t)(nn + e4) << 4));
                float4 z0 = zr[0], z1 = zr[1], z2 = zr[2], z3 = zr[3];
                acc[0]  += e;
                acc[1]  += e * z0.x; acc[2]  += e * z0.y; acc[3]  += e * z0.z; acc[4]  += e * z0.w;
                acc[5]  += e * z1.x; acc[6]  += e * z1.y; acc[7]  += e * z1.z; acc[8]  += e * z1.w;
                acc[9]  += e * z2.x; acc[10] += e * z2.y; acc[11] += e * z2.z; acc[12] += e * z2.w;
                acc[13] += e * z3.x; acc[14] += e * z3.y; acc[15] += e * z3.z; acc[16] += e * z3.w;
            }
        }
    }

    __shared__ float red[8][32][NCH];
#pragma unroll
    for (int k = 0; k < NCH; k++) red[w][lane][k] = acc[k];
    __syncthreads();

    const int sbase = blockIdx.x * 32;
    for (int idx = t; idx < 32 * NCH; idx += 256) {
        int ln = idx & 31, k = idx >> 5;
        int ss = sbase + ln;
        if (ss < S) {
            float v = 0.0f;
#pragma unroll
            for (int ww = 0; ww < 8; ww++) v += red[ww][ln][k];
            float* Gb = g_G4 + (size_t)bb * 4 * NCH * S_PAD;
#pragma unroll
            for (int r = 0; r < 4; r++) {
                int x = ss - r;
                if (x >= 0) Gb[(r * NCH + k) * S_PAD + x] = v;
            }
        }
    }
}

// ---------------------------------------------------------------------------
// Kernel B: 2 rows (i0, i0+4; same rotation class) x 1024 cols per block.
// Thread t owns j = 4t..4t+3. Rotation copy (i&3) -> every per-channel G read
// is one aligned LDG.128; row 2 hits L1 on row 1's lines (halves L2 reads).
// ---------------------------------------------------------------------------
__global__ void __launch_bounds__(256) kernel_out(
    const float* __restrict__ x_grid, const float* __restrict__ log_scale,
    float* __restrict__ out, int m)
{
    const int gx  = blockIdx.x;
    const int bb  = blockIdx.y;
    const int i0  = (gx >> 2) * 8 + (gx & 3);
    const int t   = threadIdx.x;
    const int j0  = t << 2;

    const float4 xj = ((const float4*)x_grid)[t];
    const float  inv4s2 = 0.25f / __expf(2.0f * log_scale[0]);

    const int ri = i0 & 3;
    const float* __restrict__ Gr =
        g_G4 + ((size_t)(bb * 4 + ri) * NCH) * S_PAD + (i0 - ri) + j0;

    const size_t chs = (size_t)m * m;

#pragma unroll
    for (int rr = 0; rr < 2; rr++) {
        const int i = i0 + 4 * rr;
        const float xi = x_grid[i];

        float dx, c0, c1, c2, c3;
        dx = xi - xj.x; c0 = __expf(-dx * dx * inv4s2);
        dx = xi - xj.y; c1 = __expf(-dx * dx * inv4s2);
        dx = xi - xj.z; c2 = __expf(-dx * dx * inv4s2);
        dx = xi - xj.w; c3 = __expf(-dx * dx * inv4s2);

        const float* __restrict__ G = Gr + 4 * rr;
        float* op = out + (((size_t)bb * 18) * m + i) * m + j0;

        float4 v;
        // ch0: identity
        v.x = (j0     == i) ? 1.0f : 0.0f;
        v.y = (j0 + 1 == i) ? 1.0f : 0.0f;
        v.z = (j0 + 2 == i) ? 1.0f : 0.0f;
        v.w = (j0 + 3 == i) ? 1.0f : 0.0f;
        __stcs((float4*)op, v);

        // ch1: density = C * G0
        const float4 g0 = __ldg((const float4*)G);
        float d0 = c0 * g0.x, d1 = c1 * g0.y, d2 = c2 * g0.z, d3 = c3 * g0.w;
        v.x = d0; v.y = d1; v.z = d2; v.w = d3;
        __stcs((float4*)(op + chs), v);

        // ch2..17: Gk * (C / (density + eps))
        float q0 = __fdividef(c0, d0 + EPS_DEN);
        float q1 = __fdividef(c1, d1 + EPS_DEN);
        float q2 = __fdividef(c2, d2 + EPS_DEN);
        float q3 = __fdividef(c3, d3 + EPS_DEN);

#pragma unroll
        for (int k = 1; k < NCH; k++) {
            const float4 gk = __ldg((const float4*)(G + k * S_PAD));
            v.x = gk.x * q0;
            v.y = gk.y * q1;
            v.z = gk.z * q2;
            v.w = gk.w * q3;
            __stcs((float4*)(op + (size_t)(k + 1) * chs), v);
        }
    }
}

// ---------------------------------------------------------------------------
extern "C" void kernel_launch(void* const* d_in, const int* in_sizes, int n_in,
                              void* d_out, int out_size)
{
    const float* xz        = (const float*)d_in[0];
    const float* z         = (const float*)d_in[1];
    const float* x_grid    = (const float*)d_in[2];
    const float* log_scale = (const float*)d_in[3];

    const int m = in_sizes[2];
    const long long xz_sz = in_sizes[0];
    const long long z_sz  = in_sizes[1];
    const int c = (int)(z_sz / xz_sz);                        // 16
    const long long per_b = (long long)(c + 2) * m * m;       // 18*m*m
    const long long b     = (long long)out_size / per_b;      // 4
    const long long header = (long long)out_size - b * per_b; // leading x_grid
    const int n = (int)(xz_sz / b);

    float* outp = (float*)d_out;
    if (header > 0) {
        cudaMemcpyAsync(outp, x_grid, (size_t)header * sizeof(float),
                        cudaMemcpyDeviceToDevice, 0);
        outp += header;
    }

    const int S = 2 * m - 1;
    dim3 gA((unsigned)((S + 31) / 32), (unsigned)b);
    kernel_G<<<gA, 256>>>(xz, z, x_grid, log_scale, n, m);

    dim3 gB((unsigned)(m / 2), (unsigned)b);   // 512 x 4 blocks, 2 rows each
    kernel_out<<<gB, 256>>>(x_grid, log_scale, outp, m);
}

// round 5
// speedup vs baseline: 1.3466x; 1.2162x over previous
#include <cuda_runtime.h>
#include <math.h>

// SetConv2dEncoder via Gaussian product factorization:
//   out[b,k,i,j] = C(i,j) * G[b,k,i+j],  C = exp(-(xi-xj)^2/(4 s2)),
//   G[b,k,s]     = sum_n zc[b,n,k] * exp(-(p_s - u_n)^2 / s2)
// kernel_G: warp-level deterministic compaction of the ~16% active points,
// then dense accumulation. kernel_out: unchanged R4 streamer (write-bound).

#define S_PAD   2048
#define NCH     17
#define EPS_DEN 1e-8f

// 4 batches x 4 rotations x 17 ch x 2048: copy r holds G[s] at index s-r.
__device__ __align__(16) float g_G4[4 * 4 * NCH * S_PAD];

// ---------------------------------------------------------------------------
// Kernel A: block = 32 consecutive s (lane = s), 8 warps split n.
// Phase 1: order-preserving ballot compaction of points inside the block's
// Gaussian window (~16% of n). Phase 2: dense 17-channel accumulation over
// the compacted list. smem reduce across warps, write 4 rotated copies.
// ---------------------------------------------------------------------------
__global__ void __launch_bounds__(256) kernel_G(
    const float* __restrict__ xz, const float* __restrict__ z,
    const float* __restrict__ x_grid, const float* __restrict__ log_scale,
    int n, int m)
{
    const int S    = 2 * m - 1;
    const int t    = threadIdx.x;
    const int lane = t & 31;
    const int w    = t >> 5;
    const int bb   = blockIdx.y;
    const int sb   = blockIdx.x * 32;

    const int s  = sb + lane;
    const int se = (s < S) ? s : (S - 1);
    const int s0 = se >> 1;

    const float s2     = __expf(2.0f * log_scale[0]);
    const float inv_s2 = 1.0f / s2;
    const float p      = 0.5f * (x_grid[s0] + x_grid[se - s0]);

    // block-wide acceptance window: [p(sb)-r, p(sb+31)+r], r = sqrt(80*s2)
    const float x0   = x_grid[0];
    const float step = (x_grid[m - 1] - x0) / (float)(m - 1);
    const float r    = sqrtf(80.0f * s2) + fabsf(step);   // margin for p rounding
    const int   shi  = (sb + 31 < S) ? sb + 31 : S - 1;
    const float lo   = x0 + 0.5f * (float)sb  * step - r;
    const float hi   = x0 + 0.5f * (float)shi * step + r;

    __shared__ float su[8][132];
    __shared__ int   sn[8][132];
    __shared__ float red[8][32][NCH];

    const float* __restrict__ xzb = xz + (size_t)bb * n;
    const float* __restrict__ zb  = z  + (size_t)bb * n * 16;

    // ---- phase 1: compact this warp's n-chunk (order-preserving) ----
    const int nc = n >> 3;
    const int n0 = w * nc;
    int cnt = 0;
    for (int base = 0; base < nc; base += 32) {
        const int  nn  = n0 + base + lane;
        const float u  = __ldg(xzb + nn);
        const bool act = (u >= lo) && (u <= hi);
        const unsigned mask = __ballot_sync(0xffffffffu, act);
        if (act) {
            int pos = cnt + __popc(mask & ((1u << lane) - 1u));
            su[w][pos] = u;
            sn[w][pos] = nn;
        }
        cnt += __popc(mask);
    }

    // ---- phase 2: dense accumulation over compacted list ----
    float acc[NCH];
#pragma unroll
    for (int k = 0; k < NCH; k++) acc[k] = 0.0f;

    for (int idx = 0; idx < cnt; idx++) {
        const float u  = su[w][idx];            // warp-uniform LDS
        const int   nn = sn[w][idx];
        const float d  = p - u;
        const float e  = __expf(-d * d * inv_s2);
        const float4* zr = (const float4*)(zb + ((size_t)nn << 4));
        const float4 z0 = zr[0], z1 = zr[1], z2 = zr[2], z3 = zr[3];
        acc[0]  += e;
        acc[1]  += e * z0.x; acc[2]  += e * z0.y; acc[3]  += e * z0.z; acc[4]  += e * z0.w;
        acc[5]  += e * z1.x; acc[6]  += e * z1.y; acc[7]  += e * z1.z; acc[8]  += e * z1.w;
        acc[9]  += e * z2.x; acc[10] += e * z2.y; acc[11] += e * z2.z; acc[12] += e * z2.w;
        acc[13] += e * z3.x; acc[14] += e * z3.y; acc[15] += e * z3.z; acc[16] += e * z3.w;
    }

#pragma unroll
    for (int k = 0; k < NCH; k++) red[w][lane][k] = acc[k];
    __syncthreads();

    for (int idx = t; idx < 32 * NCH; idx += 256) {
        const int ln = idx & 31, k = idx >> 5;
        const int ss = sb + ln;
        if (ss < S) {
            float v = 0.0f;
#pragma unroll
            for (int ww = 0; ww < 8; ww++) v += red[ww][ln][k];
            float* Gb = g_G4 + (size_t)bb * 4 * NCH * S_PAD;
#pragma unroll
            for (int rr = 0; rr < 4; rr++) {
                const int x = ss - rr;
                if (x >= 0) Gb[(rr * NCH + k) * S_PAD + x] = v;
            }
        }
    }
}

// ---------------------------------------------------------------------------
// Kernel B (unchanged from R4): 2 rows (i0, i0+4) x 1024 cols per block.
// Rotation copy (i&3) -> every per-channel G read is one aligned LDG.128.
// ---------------------------------------------------------------------------
__global__ void __launch_bounds__(256) kernel_out(
    const float* __restrict__ x_grid, const float* __restrict__ log_scale,
    float* __restrict__ out, int m)
{
    const int gx  = blockIdx.x;
    const int bb  = blockIdx.y;
    const int i0  = (gx >> 2) * 8 + (gx & 3);
    const int t   = threadIdx.x;
    const int j0  = t << 2;

    const float4 xj = ((const float4*)x_grid)[t];
    const float  inv4s2 = 0.25f / __expf(2.0f * log_scale[0]);

    const int ri = i0 & 3;
    const float* __restrict__ Gr =
        g_G4 + ((size_t)(bb * 4 + ri) * NCH) * S_PAD + (i0 - ri) + j0;

    const size_t chs = (size_t)m * m;

#pragma unroll
    for (int rr = 0; rr < 2; rr++) {
        const int i = i0 + 4 * rr;
        const float xi = x_grid[i];

        float dx, c0, c1, c2, c3;
        dx = xi - xj.x; c0 = __expf(-dx * dx * inv4s2);
        dx = xi - xj.y; c1 = __expf(-dx * dx * inv4s2);
        dx = xi - xj.z; c2 = __expf(-dx * dx * inv4s2);
        dx = xi - xj.w; c3 = __expf(-dx * dx * inv4s2);

        const float* __restrict__ G = Gr + 4 * rr;
        float* op = out + (((size_t)bb * 18) * m + i) * m + j0;

        float4 v;
        v.x = (j0     == i) ? 1.0f : 0.0f;
        v.y = (j0 + 1 == i) ? 1.0f : 0.0f;
        v.z = (j0 + 2 == i) ? 1.0f : 0.0f;
        v.w = (j0 + 3 == i) ? 1.0f : 0.0f;
        __stcs((float4*)op, v);

        const float4 g0 = __ldg((const float4*)G);
        float d0 = c0 * g0.x, d1 = c1 * g0.y, d2 = c2 * g0.z, d3 = c3 * g0.w;
        v.x = d0; v.y = d1; v.z = d2; v.w = d3;
        __stcs((float4*)(op + chs), v);

        float q0 = __fdividef(c0, d0 + EPS_DEN);
        float q1 = __fdividef(c1, d1 + EPS_DEN);
        float q2 = __fdividef(c2, d2 + EPS_DEN);
        float q3 = __fdividef(c3, d3 + EPS_DEN);

#pragma unroll
        for (int k = 1; k < NCH; k++) {
            const float4 gk = __ldg((const float4*)(G + k * S_PAD));
            v.x = gk.x * q0;
            v.y = gk.y * q1;
            v.z = gk.z * q2;
            v.w = gk.w * q3;
            __stcs((float4*)(op + (size_t)(k + 1) * chs), v);
        }
    }
}

// ---------------------------------------------------------------------------
extern "C" void kernel_launch(void* const* d_in, const int* in_sizes, int n_in,
                              void* d_out, int out_size)
{
    const float* xz        = (const float*)d_in[0];
    const float* z         = (const float*)d_in[1];
    const float* x_grid    = (const float*)d_in[2];
    const float* log_scale = (const float*)d_in[3];

    const int m = in_sizes[2];
    const long long xz_sz = in_sizes[0];
    const long long z_sz  = in_sizes[1];
    const int c = (int)(z_sz / xz_sz);                        // 16
    const long long per_b = (long long)(c + 2) * m * m;       // 18*m*m
    const long long b     = (long long)out_size / per_b;      // 4
    const long long header = (long long)out_size - b * per_b; // leading x_grid
    const int n = (int)(xz_sz / b);

    float* outp = (float*)d_out;
    if (header > 0) {
        cudaMemcpyAsync(outp, x_grid, (size_t)header * sizeof(float),
                        cudaMemcpyDeviceToDevice, 0);
        outp += header;
    }

    const int S = 2 * m - 1;
    dim3 gA((unsigned)((S + 31) / 32), (unsigned)b);
    kernel_G<<<gA, 256>>>(xz, z, x_grid, log_scale, n, m);

    dim3 gB((unsigned)(m / 2), (unsigned)b);   // 512 x 4 blocks, 2 rows each
    kernel_out<<<gB, 256>>>(x_grid, log_scale, outp, m);
}